// round 2
// baseline (speedup 1.0000x reference)
#include <cuda_runtime.h>
#include <math.h>

#define D_MODEL 1024
#define T_SEQ   2048
#define B_BATCH 4

// Scratch (allocation-free rule: __device__ globals)
__device__ float g_qkv[(size_t)B_BATCH * T_SEQ * 3 * D_MODEL];   // 96 MB
__device__ float g_scores[(size_t)B_BATCH * T_SEQ * T_SEQ];      // 64 MB
__device__ float g_att_out[(size_t)B_BATCH * T_SEQ * D_MODEL];   // 32 MB

// ---------------------------------------------------------------------------
// Tiled SGEMM: C[M,N] = scale * (A[M,K] @ B) (+ bias), row-major.
// TRANSB:       B is [N,K] row-major (NT gemm, used for Q@K^T)
// SKIP_UPPER:   cull blocks strictly above the causal diagonal (scores)
// KEND_CAUSAL:  K-loop stops at row0+BM (att@V: columns beyond are zeros)
// BM=BN=128, BK=8, 256 threads, 8x8 microtile per thread.
// All problem dims are multiples of 128/8 -> no bounds checks.
// ---------------------------------------------------------------------------
template<bool TRANSB, bool SKIP_UPPER, bool KEND_CAUSAL, bool BIAS>
__global__ __launch_bounds__(256) void sgemm_k(
    const float* __restrict__ A, const float* __restrict__ B,
    float* __restrict__ C, const float* __restrict__ bias,
    int K, int lda, int ldb, int ldc,
    long batchA, long batchB, long batchC, float scale)
{
    constexpr int BM = 128, BN = 128, BK = 8, TM = 8, TN = 8;

    const int row0 = blockIdx.y * BM;
    const int col0 = blockIdx.x * BN;

    if (SKIP_UPPER) {
        // block fully above diagonal: no s<=t entries -> softmax never reads it
        if (col0 > row0 + BM - 1) return;
    }

    A += (long)blockIdx.z * batchA + (long)row0 * lda;
    B += (long)blockIdx.z * batchB;
    C += (long)blockIdx.z * batchC + (long)row0 * ldc + col0;
    if (!TRANSB) B += col0;
    else         B += (long)col0 * ldb;

    __shared__ float As[BK][BM];
    __shared__ float Bs[BK][BN];

    const int tid  = threadIdx.x;
    const int arow = tid >> 1;        // 0..127
    const int acol = (tid & 1) * 4;   // 0 or 4

    const int ty = tid >> 4;          // 0..15
    const int tx = tid & 15;          // 0..15

    float acc[TM][TN];
    #pragma unroll
    for (int i = 0; i < TM; i++)
        #pragma unroll
        for (int j = 0; j < TN; j++) acc[i][j] = 0.f;

    int Kend = K;
    if (KEND_CAUSAL) { int ke = row0 + BM; Kend = ke < K ? ke : K; }

    for (int k0 = 0; k0 < Kend; k0 += BK) {
        // load A tile (transposed into smem)
        float4 av = *(const float4*)(A + (long)arow * lda + k0 + acol);
        As[acol + 0][arow] = av.x;
        As[acol + 1][arow] = av.y;
        As[acol + 2][arow] = av.z;
        As[acol + 3][arow] = av.w;

        if (!TRANSB) {
            const int brow = tid >> 5;          // 0..7
            const int bcol = (tid & 31) * 4;    // 0..124
            float4 bv = *(const float4*)(B + (long)(k0 + brow) * ldb + bcol);
            *(float4*)(&Bs[brow][bcol]) = bv;
        } else {
            float4 bv = *(const float4*)(B + (long)arow * ldb + k0 + acol);
            Bs[acol + 0][arow] = bv.x;
            Bs[acol + 1][arow] = bv.y;
            Bs[acol + 2][arow] = bv.z;
            Bs[acol + 3][arow] = bv.w;
        }
        __syncthreads();

        #pragma unroll
        for (int kk = 0; kk < BK; kk++) {
            float a[TM], b[TN];
            *(float4*)&a[0] = *(const float4*)&As[kk][ty * TM];
            *(float4*)&a[4] = *(const float4*)&As[kk][ty * TM + 4];
            *(float4*)&b[0] = *(const float4*)&Bs[kk][tx * TN];
            *(float4*)&b[4] = *(const float4*)&Bs[kk][tx * TN + 4];
            #pragma unroll
            for (int i = 0; i < TM; i++)
                #pragma unroll
                for (int j = 0; j < TN; j++)
                    acc[i][j] = fmaf(a[i], b[j], acc[i][j]);
        }
        __syncthreads();
    }

    #pragma unroll
    for (int i = 0; i < TM; i++) {
        float* crow = C + (long)(ty * TM + i) * ldc + tx * TN;
        #pragma unroll
        for (int j = 0; j < TN; j++) {
            float v = acc[i][j] * scale;
            if (BIAS) v += bias[col0 + tx * TN + j];
            crow[j] = v;
        }
    }
}

// ---------------------------------------------------------------------------
// Causal softmax over scores rows. Row t has t+1 valid entries; the tail
// [t+1, T) is written as exact zero so att@V can treat rows as dense.
// One block (256 threads) per (t, b).
// ---------------------------------------------------------------------------
__global__ __launch_bounds__(256) void softmax_causal_k(float* __restrict__ scores)
{
    const int t = blockIdx.x;
    const int b = blockIdx.y;
    float* row = scores + ((size_t)b * T_SEQ + t) * T_SEQ;
    const int n   = t + 1;
    const int tid = threadIdx.x;

    __shared__ float red[256];

    // max
    float m = -INFINITY;
    for (int i = tid; i < n; i += 256) m = fmaxf(m, row[i]);
    red[tid] = m; __syncthreads();
    for (int s = 128; s > 0; s >>= 1) {
        if (tid < s) red[tid] = fmaxf(red[tid], red[tid + s]);
        __syncthreads();
    }
    m = red[0]; __syncthreads();

    // exp + sum
    float sum = 0.f;
    for (int i = tid; i < n; i += 256) {
        float e = __expf(row[i] - m);
        row[i] = e;
        sum += e;
    }
    red[tid] = sum; __syncthreads();
    for (int s = 128; s > 0; s >>= 1) {
        if (tid < s) red[tid] += red[tid + s];
        __syncthreads();
    }
    const float inv = 1.f / red[0];

    // normalize + zero causal tail
    for (int i = tid; i < T_SEQ; i += 256) {
        if (i < n) row[i] *= inv;
        else       row[i] = 0.f;
    }
}

extern "C" void kernel_launch(void* const* d_in, const int* in_sizes, int n_in,
                              void* d_out, int out_size)
{
    (void)in_sizes; (void)n_in; (void)out_size;
    const float* x      = (const float*)d_in[0];  // [4,2048,1024]
    const float* w_qkv  = (const float*)d_in[1];  // [1024,3072]
    const float* w_proj = (const float*)d_in[2];  // [1024,1024]
    const float* b_proj = (const float*)d_in[3];  // [1024]
    float* out          = (float*)d_out;          // [4,2048,1024]

    float *qkv, *scores, *att_out;
    cudaGetSymbolAddress((void**)&qkv,     g_qkv);
    cudaGetSymbolAddress((void**)&scores,  g_scores);
    cudaGetSymbolAddress((void**)&att_out, g_att_out);

    const int D = D_MODEL, T = T_SEQ;
    const dim3 blk(256);

    // 1) QKV = X @ Wqkv : [8192,3072], K=1024
    sgemm_k<false, false, false, false><<<dim3(3 * D / 128, B_BATCH * T / 128, 1), blk>>>(
        x, w_qkv, qkv, nullptr, D, D, 3 * D, 3 * D, 0, 0, 0, 1.f);

    // 2) scores = Q @ K^T / 32, causal block culling : per batch [2048,2048], K=1024
    sgemm_k<true, true, false, false><<<dim3(T / 128, T / 128, B_BATCH), blk>>>(
        qkv,                 /* Q: rows stride 3D */
        qkv + D,             /* K: rows stride 3D */
        scores, nullptr, D, 3 * D, 3 * D, T,
        (long)T * 3 * D, (long)T * 3 * D, (long)T * T, 1.f / 32.f);

    // 3) causal softmax in-place
    softmax_causal_k<<<dim3(T, B_BATCH), blk>>>(scores);

    // 4) att_out = P @ V : per batch [2048,1024], K=2048 with causal K-end
    sgemm_k<false, false, true, false><<<dim3(D / 128, T / 128, B_BATCH), blk>>>(
        scores, qkv + 2 * D, att_out, nullptr, T, T, 3 * D, D,
        (long)T * T, (long)T * 3 * D, (long)T * D, 1.f);

    // 5) out = att_out @ Wproj + b : [8192,1024], K=1024
    sgemm_k<false, false, false, true><<<dim3(D / 128, B_BATCH * T / 128, 1), blk>>>(
        att_out, w_proj, out, b_proj, D, D, D, D, 0, 0, 0, 1.f);
}

// round 4
// speedup vs baseline: 3.3343x; 3.3343x over previous
#include <cuda_runtime.h>
#include <cstdint>
#include <math.h>

#define D_MODEL 1024
#define T_SEQ   2048
#define B_BATCH 4

// Scratch (allocation-free rule: __device__ globals)
__device__ float g_qkv[(size_t)B_BATCH * T_SEQ * 3 * D_MODEL];   // 96 MB
__device__ float g_scores[(size_t)B_BATCH * T_SEQ * T_SEQ];      // 64 MB
__device__ float g_att[(size_t)B_BATCH * T_SEQ * D_MODEL];       // 32 MB

// fp32 -> tf32 (round-to-nearest) kept in a 32-bit container
__device__ __forceinline__ float totf32(float x) {
    uint32_t r;
    asm("cvt.rna.tf32.f32 %0, %1;" : "=r"(r) : "f"(x));
    return __uint_as_float(r);
}

__device__ __forceinline__ float4 cvt4(float4 v) {
    return make_float4(totf32(v.x), totf32(v.y), totf32(v.z), totf32(v.w));
}

// m16n8k8 tf32 mma, row.col, fp32 accumulate
__device__ __forceinline__ void mma8(float* acc, const uint32_t* a, const uint32_t* b) {
    asm volatile(
        "mma.sync.aligned.m16n8k8.row.col.f32.tf32.tf32.f32 "
        "{%0,%1,%2,%3}, {%4,%5,%6,%7}, {%8,%9}, {%0,%1,%2,%3};"
        : "+f"(acc[0]), "+f"(acc[1]), "+f"(acc[2]), "+f"(acc[3])
        : "r"(a[0]), "r"(a[1]), "r"(a[2]), "r"(a[3]), "r"(b[0]), "r"(b[1]));
}

// ---------------------------------------------------------------------------
// tf32 tensor GEMM: C[M,N] = scale * (A[M,K] @ op(B)) (+ bias), fp32 I/O.
// BNMAJ=1: B is [K,N] row-major -> Bs stored [k][n] (direct coalesced copy)
// BNMAJ=0: B is [N,K] row-major (Q@K^T) -> Bs stored [n][k] (same layout as A)
// SKIPUP:  cull blocks with col0 > row0 (causal scores)
// KCAUSAL: K-loop ends at row0+128 (P@V; softmax zeroed the tails)
// 128x128 tile, BK=32, 256 thr (8 warps as 2Mx4N, warp tile 64x32).
// Register-double-buffered global loads, 2 smem buffers, tf32 cvt at staging.
// ---------------------------------------------------------------------------
template<int BNMAJ, bool SKIPUP, bool KCAUSAL, bool BIAS>
__global__ __launch_bounds__(256) void mm_tc(
    const float* __restrict__ A, const float* __restrict__ B,
    float* __restrict__ C, const float* __restrict__ bias,
    int K, int lda, int ldb, int ldc,
    long bA, long bB, long bC, float scale)
{
    constexpr int BM = 128, BN = 128, BK = 32;
    constexpr int AST = 36;    // A smem row stride (floats), padded
    constexpr int BSTN = 136;  // B smem row stride for [k][n] layout
    constexpr int ABUF = 4608; // 128*36 floats per buffer
    constexpr int BBUF = 4608; // max(32*136, 128*36)

    extern __shared__ float sm[];
    const int row0 = blockIdx.y * BM, col0 = blockIdx.x * BN;
    if (SKIPUP && col0 > row0) return;

    A += (long)blockIdx.z * bA + (long)row0 * lda;
    B += (long)blockIdx.z * bB + (BNMAJ ? (long)col0 : (long)col0 * ldb);
    C += (long)blockIdx.z * bC + (long)row0 * ldc + col0;

    const int tid = threadIdx.x;
    const int wid = tid >> 5, lane = tid & 31;
    const int g = lane >> 2, t = lane & 3;          // mma group / thread-in-group
    const int mbase = (wid >> 2) * 64;              // warp M offset
    const int nbase = (wid & 3) * 32;               // warp N offset

    int Kend = K;
    if (KCAUSAL) { int ke = row0 + BM; Kend = ke < K ? ke : K; }
    const int NC = Kend / BK;

    float acc[4][4][4];
    #pragma unroll
    for (int i = 0; i < 4; i++)
        #pragma unroll
        for (int j = 0; j < 4; j++)
            #pragma unroll
            for (int q = 0; q < 4; q++) acc[i][j][q] = 0.f;

    // per-thread staging coordinates
    const int am = tid >> 3, ak4 = tid & 7;         // A: [m][k4] float4
    const int bkk = tid >> 5, bn4 = tid & 31;       // B NN: [k][n4] float4

    float4 av[4], bv[4];

    auto ldg_chunk = [&](int c) {
        const int k0 = c * BK;
        #pragma unroll
        for (int p = 0; p < 4; p++)
            av[p] = *(const float4*)(A + (long)(am + p * 32) * lda + k0 + ak4 * 4);
        if (BNMAJ) {
            #pragma unroll
            for (int p = 0; p < 4; p++)
                bv[p] = *(const float4*)(B + (long)(k0 + bkk + p * 8) * ldb + bn4 * 4);
        } else {
            #pragma unroll
            for (int p = 0; p < 4; p++)
                bv[p] = *(const float4*)(B + (long)(am + p * 32) * ldb + k0 + ak4 * 4);
        }
    };
    auto sts_chunk = [&](int b) {
        float* As = sm + b * ABUF;
        float* Bs = sm + 2 * ABUF + b * BBUF;
        #pragma unroll
        for (int p = 0; p < 4; p++)
            *(float4*)(As + (am + p * 32) * AST + ak4 * 4) = cvt4(av[p]);
        if (BNMAJ) {
            #pragma unroll
            for (int p = 0; p < 4; p++)
                *(float4*)(Bs + (bkk + p * 8) * BSTN + bn4 * 4) = cvt4(bv[p]);
        } else {
            #pragma unroll
            for (int p = 0; p < 4; p++)
                *(float4*)(Bs + (am + p * 32) * AST + ak4 * 4) = cvt4(bv[p]);
        }
    };

    ldg_chunk(0);
    sts_chunk(0);
    __syncthreads();

    for (int c = 0; c < NC; c++) {
        const int b = c & 1;
        if (c + 1 < NC) ldg_chunk(c + 1);

        const uint32_t* As = (const uint32_t*)(sm + b * ABUF);
        const uint32_t* Bs = (const uint32_t*)(sm + 2 * ABUF + b * BBUF);
        #pragma unroll
        for (int ks = 0; ks < 4; ks++) {
            const int k8 = ks * 8;
            uint32_t a[4][4], bb[4][2];
            #pragma unroll
            for (int mt = 0; mt < 4; mt++) {
                const uint32_t* r0p = As + (mbase + mt * 16 + g) * AST + k8 + t;
                const uint32_t* r1p = As + (mbase + mt * 16 + g + 8) * AST + k8 + t;
                a[mt][0] = r0p[0]; a[mt][1] = r1p[0];
                a[mt][2] = r0p[4]; a[mt][3] = r1p[4];
            }
            #pragma unroll
            for (int nt = 0; nt < 4; nt++) {
                if (BNMAJ) {
                    bb[nt][0] = Bs[(k8 + t) * BSTN + nbase + nt * 8 + g];
                    bb[nt][1] = Bs[(k8 + t + 4) * BSTN + nbase + nt * 8 + g];
                } else {
                    const uint32_t* np = Bs + (nbase + nt * 8 + g) * AST + k8 + t;
                    bb[nt][0] = np[0];
                    bb[nt][1] = np[4];
                }
            }
            #pragma unroll
            for (int mt = 0; mt < 4; mt++)
                #pragma unroll
                for (int nt = 0; nt < 4; nt++)
                    mma8(acc[mt][nt], a[mt], bb[nt]);
        }

        if (c + 1 < NC) {
            sts_chunk((c + 1) & 1);
            __syncthreads();
        }
    }

    // epilogue
    #pragma unroll
    for (int mt = 0; mt < 4; mt++) {
        const int r0 = mbase + mt * 16 + g;
        #pragma unroll
        for (int nt = 0; nt < 4; nt++) {
            const int cc = nbase + nt * 8 + 2 * t;
            float bx = 0.f, by = 0.f;
            if (BIAS) { bx = bias[col0 + cc]; by = bias[col0 + cc + 1]; }
            float2 v0 = make_float2(acc[mt][nt][0] * scale + bx,
                                    acc[mt][nt][1] * scale + by);
            float2 v1 = make_float2(acc[mt][nt][2] * scale + bx,
                                    acc[mt][nt][3] * scale + by);
            *(float2*)(C + (long)r0 * ldc + cc)       = v0;
            *(float2*)(C + (long)(r0 + 8) * ldc + cc) = v1;
        }
    }
}

// ---------------------------------------------------------------------------
// Causal softmax: row t has t+1 valid entries; tail zeroed so P@V is dense.
// ---------------------------------------------------------------------------
__global__ __launch_bounds__(256) void softmax_causal_k(float* __restrict__ scores)
{
    const int t = blockIdx.x;
    const int b = blockIdx.y;
    float* row = scores + ((size_t)b * T_SEQ + t) * T_SEQ;
    const int n = t + 1;
    const int tid = threadIdx.x;

    __shared__ float red[256];

    float m = -INFINITY;
    for (int i = tid; i < n; i += 256) m = fmaxf(m, row[i]);
    red[tid] = m; __syncthreads();
    for (int s = 128; s > 0; s >>= 1) {
        if (tid < s) red[tid] = fmaxf(red[tid], red[tid + s]);
        __syncthreads();
    }
    m = red[0]; __syncthreads();

    float sum = 0.f;
    for (int i = tid; i < n; i += 256) {
        float e = __expf(row[i] - m);
        row[i] = e;
        sum += e;
    }
    red[tid] = sum; __syncthreads();
    for (int s = 128; s > 0; s >>= 1) {
        if (tid < s) red[tid] += red[tid + s];
        __syncthreads();
    }
    const float inv = 1.f / red[0];

    for (int i = tid; i < T_SEQ; i += 256) {
        if (i < n) row[i] *= inv;
        else       row[i] = 0.f;
    }
}

extern "C" void kernel_launch(void* const* d_in, const int* in_sizes, int n_in,
                              void* d_out, int out_size)
{
    (void)in_sizes; (void)n_in; (void)out_size;
    const float* x      = (const float*)d_in[0];  // [4,2048,1024]
    const float* w_qkv  = (const float*)d_in[1];  // [1024,3072]
    const float* w_proj = (const float*)d_in[2];  // [1024,1024]
    const float* b_proj = (const float*)d_in[3];  // [1024]
    float* out          = (float*)d_out;          // [4,2048,1024]

    float *qkv, *scores, *att;
    cudaGetSymbolAddress((void**)&qkv,    g_qkv);
    cudaGetSymbolAddress((void**)&scores, g_scores);
    cudaGetSymbolAddress((void**)&att,    g_att);

    const int D = D_MODEL, T = T_SEQ;
    const int SMEM_BYTES = 4 * 4608 * 4;  // 73728: 2x A buf + 2x B buf
    const dim3 blk(256);

    cudaFuncSetAttribute(mm_tc<1, false, false, false>,
                         cudaFuncAttributeMaxDynamicSharedMemorySize, SMEM_BYTES);
    cudaFuncSetAttribute(mm_tc<0, true,  false, false>,
                         cudaFuncAttributeMaxDynamicSharedMemorySize, SMEM_BYTES);
    cudaFuncSetAttribute(mm_tc<1, false, true,  false>,
                         cudaFuncAttributeMaxDynamicSharedMemorySize, SMEM_BYTES);
    cudaFuncSetAttribute(mm_tc<1, false, false, true>,
                         cudaFuncAttributeMaxDynamicSharedMemorySize, SMEM_BYTES);

    // 1) QKV = X @ Wqkv : [8192,3072], K=1024, B is [K,N]
    mm_tc<1, false, false, false><<<dim3(3 * D / 128, B_BATCH * T / 128, 1), blk, SMEM_BYTES>>>(
        x, w_qkv, qkv, nullptr, D, D, 3 * D, 3 * D, 0, 0, 0, 1.f);

    // 2) scores = Q @ K^T / 32, causal block culling; B (K matrix) is [N,K]
    mm_tc<0, true, false, false><<<dim3(T / 128, T / 128, B_BATCH), blk, SMEM_BYTES>>>(
        qkv, qkv + D, scores, nullptr, D, 3 * D, 3 * D, T,
        (long)T * 3 * D, (long)T * 3 * D, (long)T * T, 1.f / 32.f);

    // 3) causal softmax in-place (zeroes tails)
    softmax_causal_k<<<dim3(T, B_BATCH), blk>>>(scores);

    // 4) att = P @ V : K=2048 with causal K-end; V is [K,N]
    mm_tc<1, false, true, false><<<dim3(D / 128, T / 128, B_BATCH), blk, SMEM_BYTES>>>(
        scores, qkv + 2 * D, att, nullptr, T, T, 3 * D, D,
        (long)T * T, (long)T * 3 * D, (long)T * D, 1.f);

    // 5) out = att @ Wproj + b : [8192,1024], K=1024, B is [K,N]
    mm_tc<1, false, false, true><<<dim3(D / 128, B_BATCH * T / 128, 1), blk, SMEM_BYTES>>>(
        att, w_proj, out, b_proj, D, D, D, D, 0, 0, 0, 1.f);
}

// round 5
// speedup vs baseline: 4.3975x; 1.3189x over previous
#include <cuda_runtime.h>
#include <cuda_fp16.h>
#include <cstdint>
#include <math.h>

#define D_MODEL 1024
#define T_SEQ   2048
#define B_BATCH 4

// Scratch (allocation-free rule: __device__ globals)
__device__ __half g_qkv[(size_t)B_BATCH * T_SEQ * 3 * D_MODEL];   // 48 MB
__device__ float  g_scores[(size_t)B_BATCH * T_SEQ * T_SEQ];      // 64 MB
__device__ __half g_p[(size_t)B_BATCH * T_SEQ * T_SEQ];           // 32 MB
__device__ __half g_att[(size_t)B_BATCH * T_SEQ * D_MODEL];       // 16 MB

__device__ __forceinline__ uint32_t pack2(float x, float y) {
    __half2 h = __floats2half2_rn(x, y);
    return *(uint32_t*)&h;
}

// m16n8k16 fp16 mma, row.col, fp32 accumulate
__device__ __forceinline__ void mma16(float* acc, const uint32_t* a, const uint32_t* b) {
    asm volatile(
        "mma.sync.aligned.m16n8k16.row.col.f32.f16.f16.f32 "
        "{%0,%1,%2,%3}, {%4,%5,%6,%7}, {%8,%9}, {%0,%1,%2,%3};"
        : "+f"(acc[0]), "+f"(acc[1]), "+f"(acc[2]), "+f"(acc[3])
        : "r"(a[0]), "r"(a[1]), "r"(a[2]), "r"(a[3]), "r"(b[0]), "r"(b[1]));
}

// ---------------------------------------------------------------------------
// fp16-operand GEMM: C[M,N] = scale * (A[M,K] @ op(B)) (+ bias), fp32 accum.
// TA/TB in {float, __half}: float inputs are cvt_rn'd to fp16 at staging.
// TC in {float, __half}.
// BNMAJ=1: B is [K,N] row-major -> Bs stored [k][n]
// BNMAJ=0: B is [N,K] row-major -> Bs stored [n][k] (same layout as A)
// SKIPUP:  cull blocks with col0 > row0 (causal scores)
// KCAUSAL: K-loop ends at row0+128 (P@V; softmax zeroed the tails)
// 128x128 tile, BK=32, 256 thr (8 warps 2Mx4N, warp tile 64x32), k16 steps.
// Register-double-buffered global loads, 2 smem buffers.
// ---------------------------------------------------------------------------
template<typename TA, typename TB, typename TC,
         int BNMAJ, bool SKIPUP, bool KCAUSAL, bool BIAS>
__global__ __launch_bounds__(256) void mm_h(
    const TA* __restrict__ A, const TB* __restrict__ B,
    TC* __restrict__ C, const float* __restrict__ bias,
    int K, int lda, int ldb, int ldc,
    long bA, long bB, long bC, float scale)
{
    constexpr int BM = 128, BK = 32;
    constexpr int AST = 40;     // A/B([n][k]) smem row stride in halves
    constexpr int BST1 = 136;   // B [k][n] smem row stride in halves
    constexpr int BUF = 5120;   // halves per buffer

    __shared__ __half sm[4 * BUF];   // As x2, Bs x2 = 40 KB

    const int row0 = blockIdx.y * BM, col0 = blockIdx.x * BM;
    if (SKIPUP && col0 > row0) return;

    A += (long)blockIdx.z * bA + (long)row0 * lda;
    B += (long)blockIdx.z * bB + (BNMAJ ? (long)col0 : (long)col0 * ldb);
    C += (long)blockIdx.z * bC + (long)row0 * ldc + col0;

    const int tid = threadIdx.x;
    const int wid = tid >> 5, lane = tid & 31;
    const int g = lane >> 2, t = lane & 3;
    const int mbase = (wid >> 2) * 64;
    const int nbase = (wid & 3) * 32;

    int Kend = K;
    if (KCAUSAL) { int ke = row0 + BM; Kend = ke < K ? ke : K; }
    const int NC = Kend / BK;

    float acc[4][4][4];
    #pragma unroll
    for (int i = 0; i < 4; i++)
        #pragma unroll
        for (int j = 0; j < 4; j++)
            #pragma unroll
            for (int q = 0; q < 4; q++) acc[i][j][q] = 0.f;

    // staging coords: tiles are 512 chunks of 8 halves; 256 thr x 2 iters
    const int am = (tid * 2) >> 3;          // will recompute per-iter below
    (void)am;

    // staging registers (unused alternates are dead-code eliminated)
    float4 fA[4]; uint4 hA[2];
    float4 fB[4]; uint4 hB[2];

    auto ldgA = [&](int c) {
        #pragma unroll
        for (int it = 0; it < 2; it++) {
            const int i = tid + it * 256;
            const int m = i >> 2, kc = i & 3;
            const TA* p = A + (long)m * lda + c * BK + kc * 8;
            if constexpr (sizeof(TA) == 2) {
                hA[it] = *(const uint4*)p;
            } else {
                fA[2 * it]     = *(const float4*)p;
                fA[2 * it + 1] = *(const float4*)(p + 4);
            }
        }
    };
    auto ldgB = [&](int c) {
        #pragma unroll
        for (int it = 0; it < 2; it++) {
            const int i = tid + it * 256;
            const TB* p;
            if (BNMAJ) {
                const int k = i >> 4, nc = i & 15;
                p = B + (long)(c * BK + k) * ldb + nc * 8;
            } else {
                const int n = i >> 2, kc = i & 3;
                p = B + (long)n * ldb + c * BK + kc * 8;
            }
            if constexpr (sizeof(TB) == 2) {
                hB[it] = *(const uint4*)p;
            } else {
                fB[2 * it]     = *(const float4*)p;
                fB[2 * it + 1] = *(const float4*)(p + 4);
            }
        }
    };
    auto stsA = [&](int b) {
        __half* As = sm + b * BUF;
        #pragma unroll
        for (int it = 0; it < 2; it++) {
            const int i = tid + it * 256;
            const int m = i >> 2, kc = i & 3;
            uint4 v;
            if constexpr (sizeof(TA) == 2) v = hA[it];
            else {
                v.x = pack2(fA[2*it].x,   fA[2*it].y);
                v.y = pack2(fA[2*it].z,   fA[2*it].w);
                v.z = pack2(fA[2*it+1].x, fA[2*it+1].y);
                v.w = pack2(fA[2*it+1].z, fA[2*it+1].w);
            }
            *(uint4*)(As + m * AST + kc * 8) = v;
        }
    };
    auto stsB = [&](int b) {
        __half* Bs = sm + 2 * BUF + b * BUF;
        #pragma unroll
        for (int it = 0; it < 2; it++) {
            const int i = tid + it * 256;
            uint4 v;
            if constexpr (sizeof(TB) == 2) v = hB[it];
            else {
                v.x = pack2(fB[2*it].x,   fB[2*it].y);
                v.y = pack2(fB[2*it].z,   fB[2*it].w);
                v.z = pack2(fB[2*it+1].x, fB[2*it+1].y);
                v.w = pack2(fB[2*it+1].z, fB[2*it+1].w);
            }
            if (BNMAJ) {
                const int k = i >> 4, nc = i & 15;
                *(uint4*)(Bs + k * BST1 + nc * 8) = v;
            } else {
                const int n = i >> 2, kc = i & 3;
                *(uint4*)(Bs + n * AST + kc * 8) = v;
            }
        }
    };

    ldgA(0); ldgB(0);
    stsA(0); stsB(0);
    __syncthreads();

    for (int c = 0; c < NC; c++) {
        const int b = c & 1;
        if (c + 1 < NC) { ldgA(c + 1); ldgB(c + 1); }

        const uint32_t* As32 = (const uint32_t*)(sm + b * BUF);
        const __half*   BsH  = sm + 2 * BUF + b * BUF;
        const uint32_t* Bs32 = (const uint32_t*)BsH;

        #pragma unroll
        for (int ks = 0; ks < 2; ks++) {            // two k16 steps per chunk
            const int w0 = ks * 8 + t;              // word offset in K-major rows
            uint32_t a[4][4], bb[4][2];
            #pragma unroll
            for (int mt = 0; mt < 4; mt++) {
                const int r = mbase + mt * 16 + g;
                a[mt][0] = As32[r * 20 + w0];
                a[mt][1] = As32[(r + 8) * 20 + w0];
                a[mt][2] = As32[r * 20 + w0 + 4];
                a[mt][3] = As32[(r + 8) * 20 + w0 + 4];
            }
            #pragma unroll
            for (int nt = 0; nt < 4; nt++) {
                const int n = nbase + nt * 8 + g;
                if (BNMAJ) {
                    const int k0 = ks * 16 + t * 2;
                    uint32_t l0 = *(const uint16_t*)(BsH + (k0    ) * BST1 + n);
                    uint32_t l1 = *(const uint16_t*)(BsH + (k0 + 1) * BST1 + n);
                    uint32_t l2 = *(const uint16_t*)(BsH + (k0 + 8) * BST1 + n);
                    uint32_t l3 = *(const uint16_t*)(BsH + (k0 + 9) * BST1 + n);
                    bb[nt][0] = l0 | (l1 << 16);
                    bb[nt][1] = l2 | (l3 << 16);
                } else {
                    bb[nt][0] = Bs32[n * 20 + w0];
                    bb[nt][1] = Bs32[n * 20 + w0 + 4];
                }
            }
            #pragma unroll
            for (int mt = 0; mt < 4; mt++)
                #pragma unroll
                for (int nt = 0; nt < 4; nt++)
                    mma16(acc[mt][nt], a[mt], bb[nt]);
        }

        if (c + 1 < NC) {
            stsA((c + 1) & 1); stsB((c + 1) & 1);
            __syncthreads();
        }
    }

    // epilogue
    #pragma unroll
    for (int mt = 0; mt < 4; mt++) {
        const int r0 = mbase + mt * 16 + g;
        #pragma unroll
        for (int nt = 0; nt < 4; nt++) {
            const int cc = nbase + nt * 8 + 2 * t;
            float bx = 0.f, by = 0.f;
            if (BIAS) { bx = bias[col0 + cc]; by = bias[col0 + cc + 1]; }
            float v00 = acc[mt][nt][0] * scale + bx;
            float v01 = acc[mt][nt][1] * scale + by;
            float v10 = acc[mt][nt][2] * scale + bx;
            float v11 = acc[mt][nt][3] * scale + by;
            if constexpr (sizeof(TC) == 2) {
                *(__half2*)((__half*)C + (long)r0 * ldc + cc) =
                    __floats2half2_rn(v00, v01);
                *(__half2*)((__half*)C + (long)(r0 + 8) * ldc + cc) =
                    __floats2half2_rn(v10, v11);
            } else {
                *(float2*)((float*)C + (long)r0 * ldc + cc) = make_float2(v00, v01);
                *(float2*)((float*)C + (long)(r0 + 8) * ldc + cc) = make_float2(v10, v11);
            }
        }
    }
}

// ---------------------------------------------------------------------------
// Causal softmax, single pass over the row (register-cached), fp32 in,
// fp16 normalized out with exact-zero tail so P@V is dense.
// ---------------------------------------------------------------------------
__global__ __launch_bounds__(256) void softmax_causal_k(
    const float* __restrict__ scores, __half* __restrict__ P)
{
    const int t = blockIdx.x;
    const int b = blockIdx.y;
    const float* row = scores + ((size_t)b * T_SEQ + t) * T_SEQ;
    __half* prow = P + ((size_t)b * T_SEQ + t) * T_SEQ;
    const int n = t + 1;
    const int tid = threadIdx.x;

    __shared__ float red[256];

    float e[T_SEQ / 256];
    float m = -INFINITY;
    #pragma unroll
    for (int j = 0; j < T_SEQ / 256; j++) {
        const int i = tid + j * 256;
        e[j] = (i < n) ? row[i] : -INFINITY;
        m = fmaxf(m, e[j]);
    }
    red[tid] = m; __syncthreads();
    for (int s = 128; s > 0; s >>= 1) {
        if (tid < s) red[tid] = fmaxf(red[tid], red[tid + s]);
        __syncthreads();
    }
    m = red[0]; __syncthreads();

    float sum = 0.f;
    #pragma unroll
    for (int j = 0; j < T_SEQ / 256; j++) {
        const int i = tid + j * 256;
        if (i < n) { e[j] = __expf(e[j] - m); sum += e[j]; }
        else e[j] = 0.f;
    }
    red[tid] = sum; __syncthreads();
    for (int s = 128; s > 0; s >>= 1) {
        if (tid < s) red[tid] += red[tid + s];
        __syncthreads();
    }
    const float inv = 1.f / red[0];

    #pragma unroll
    for (int j = 0; j < T_SEQ / 256; j++) {
        const int i = tid + j * 256;
        prow[i] = __float2half_rn(e[j] * inv);
    }
}

extern "C" void kernel_launch(void* const* d_in, const int* in_sizes, int n_in,
                              void* d_out, int out_size)
{
    (void)in_sizes; (void)n_in; (void)out_size;
    const float* x      = (const float*)d_in[0];  // [4,2048,1024]
    const float* w_qkv  = (const float*)d_in[1];  // [1024,3072]
    const float* w_proj = (const float*)d_in[2];  // [1024,1024]
    const float* b_proj = (const float*)d_in[3];  // [1024]
    float* out          = (float*)d_out;          // [4,2048,1024]

    __half *qkv, *p, *att;
    float *scores;
    cudaGetSymbolAddress((void**)&qkv,    g_qkv);
    cudaGetSymbolAddress((void**)&scores, g_scores);
    cudaGetSymbolAddress((void**)&p,      g_p);
    cudaGetSymbolAddress((void**)&att,    g_att);

    const int D = D_MODEL, T = T_SEQ;
    const dim3 blk(256);

    // 1) QKV = X @ Wqkv -> fp16 : [8192,3072], K=1024, B is [K,N] fp32
    mm_h<float, float, __half, 1, false, false, false>
        <<<dim3(3 * D / 128, B_BATCH * T / 128, 1), blk>>>(
        x, w_qkv, qkv, nullptr, D, D, 3 * D, 3 * D, 0, 0, 0, 1.f);

    // 2) scores = Q @ K^T / 32 (fp32 out), causal block culling; K-matrix [N,K] fp16
    mm_h<__half, __half, float, 0, true, false, false>
        <<<dim3(T / 128, T / 128, B_BATCH), blk>>>(
        qkv, qkv + D, scores, nullptr, D, 3 * D, 3 * D, T,
        (long)T * 3 * D, (long)T * 3 * D, (long)T * T, 1.f / 32.f);

    // 3) causal softmax: fp32 scores -> normalized fp16 P (zero tails)
    softmax_causal_k<<<dim3(T, B_BATCH), blk>>>(scores, p);

    // 4) att = P @ V -> fp16 : K=2048 with causal K-end; V is [K,N] fp16
    mm_h<__half, __half, __half, 1, false, true, false>
        <<<dim3(D / 128, T / 128, B_BATCH), blk>>>(
        p, qkv + 2 * D, att, nullptr, T, T, 3 * D, D,
        (long)T * T, (long)T * 3 * D, (long)T * D, 1.f);

    // 5) out = att @ Wproj + b : [8192,1024], K=1024, W fp32 [K,N]
    mm_h<__half, float, float, 1, false, false, true>
        <<<dim3(D / 128, B_BATCH * T / 128, 1), blk>>>(
        att, w_proj, out, b_proj, D, D, D, D, 0, 0, 0, 1.f);
}

// round 6
// speedup vs baseline: 7.9496x; 1.8077x over previous
#include <cuda_runtime.h>
#include <cuda_fp16.h>
#include <cstdint>
#include <math.h>

#define D_MODEL 1024
#define T_SEQ   2048
#define B_BATCH 4

// Scratch (allocation-free rule: __device__ globals)
__device__ __half g_xh[(size_t)B_BATCH * T_SEQ * D_MODEL];        // 16 MB
__device__ __half g_wqkvh[(size_t)D_MODEL * 3 * D_MODEL];         // 6 MB
__device__ __half g_wprojh[(size_t)D_MODEL * D_MODEL];            // 2 MB
__device__ __half g_qkv[(size_t)B_BATCH * T_SEQ * 3 * D_MODEL];   // 48 MB
__device__ float  g_scores[(size_t)B_BATCH * T_SEQ * T_SEQ];      // 64 MB
__device__ __half g_p[(size_t)B_BATCH * T_SEQ * T_SEQ];           // 32 MB
__device__ __half g_att[(size_t)B_BATCH * T_SEQ * D_MODEL];       // 16 MB

__device__ __forceinline__ uint32_t smem_u32(const void* p) {
    uint32_t a;
    asm("{ .reg .u64 t; cvta.to.shared.u64 t, %1; cvt.u32.u64 %0, t; }"
        : "=r"(a) : "l"(p));
    return a;
}

__device__ __forceinline__ uint32_t pack2(float x, float y) {
    __half2 h = __floats2half2_rn(x, y);
    return *(uint32_t*)&h;
}

__device__ __forceinline__ void mma16(float* acc, const uint32_t* a, const uint32_t* b) {
    asm volatile(
        "mma.sync.aligned.m16n8k16.row.col.f32.f16.f16.f32 "
        "{%0,%1,%2,%3}, {%4,%5,%6,%7}, {%8,%9}, {%0,%1,%2,%3};"
        : "+f"(acc[0]), "+f"(acc[1]), "+f"(acc[2]), "+f"(acc[3])
        : "r"(a[0]), "r"(a[1]), "r"(a[2]), "r"(a[3]), "r"(b[0]), "r"(b[1]));
}

__device__ __forceinline__ void ldsm4(uint32_t* r, uint32_t a) {
    asm volatile("ldmatrix.sync.aligned.m8n8.x4.shared.b16 {%0,%1,%2,%3}, [%4];"
        : "=r"(r[0]), "=r"(r[1]), "=r"(r[2]), "=r"(r[3]) : "r"(a));
}
__device__ __forceinline__ void ldsm4t(uint32_t* r, uint32_t a) {
    asm volatile("ldmatrix.sync.aligned.m8n8.x4.trans.shared.b16 {%0,%1,%2,%3}, [%4];"
        : "=r"(r[0]), "=r"(r[1]), "=r"(r[2]), "=r"(r[3]) : "r"(a));
}

__device__ __forceinline__ void cpa16(uint32_t dst, const __half* src) {
    asm volatile("cp.async.cg.shared.global [%0], [%1], 16;"
        :: "r"(dst), "l"(__cvta_generic_to_global(src)));
}
#define CP_COMMIT() asm volatile("cp.async.commit_group;" ::: "memory")
#define CP_WAIT(n)  asm volatile("cp.async.wait_group %0;" :: "n"(n) : "memory")

// ---------------------------------------------------------------------------
// fp16 GEMM, fp32 accumulate: C = scale*(A @ op(B)) (+bias).
// A: [M,K] fp16 row-major.
// BTRANS=1: B is [K,N] -> smem [k][n] stride 136, ldmatrix.trans
// BTRANS=0: B is [N,K] -> smem [n][k] stride 40, ldmatrix (same as A)
// SKIPUP:  cull blocks col0 > row0.  KCAUSAL: K ends at row0+128.
// REVY:    reverse blockIdx.y so heavy (large-row0) tiles launch first.
// 128x128 tile, BK=32, 4-stage cp.async pipeline, 256 thr (8 warps 2Mx4N).
// ---------------------------------------------------------------------------
template<typename TC, int BTRANS, bool SKIPUP, bool KCAUSAL, bool BIAS, bool REVY>
__global__ __launch_bounds__(256) void mm_h(
    const __half* __restrict__ A, const __half* __restrict__ B,
    TC* __restrict__ C, const float* __restrict__ bias,
    int K, int lda, int ldb, int ldc,
    long bA, long bB, long bC, float scale)
{
    constexpr int BM = 128, BK = 32, S = 4;
    constexpr int AST = 40, BSTT = 136, BSTN = 40;   // smem strides (halves)
    constexpr int STG = 20480;                       // bytes per stage (A 10240 + B 10240)
    extern __shared__ char dsm[];

    const int by = REVY ? (gridDim.y - 1 - blockIdx.y) : blockIdx.y;
    const int row0 = by * BM, col0 = blockIdx.x * BM;
    if (SKIPUP && col0 > row0) return;

    A += (long)blockIdx.z * bA + (long)row0 * lda;
    B += (long)blockIdx.z * bB + (BTRANS ? (long)col0 : (long)col0 * ldb);
    C += (long)blockIdx.z * bC + (long)row0 * ldc + col0;

    const int tid = threadIdx.x, wid = tid >> 5, lane = tid & 31;
    const int g = lane >> 2, t = lane & 3;
    const int grp = lane >> 3, li = lane & 7;
    const int mbase = (wid >> 2) * 64;
    const int nbase = (wid & 3) * 32;

    int Kend = K;
    if (KCAUSAL) { int ke = row0 + BM; Kend = ke < K ? ke : K; }
    const int NC = Kend / BK;

    const uint32_t smb = smem_u32(dsm);

    // cp.async per-thread coords
    const int amRow = tid >> 2, ak4 = tid & 3;
    const __half* aSrc = A + (long)amRow * lda + ak4 * 8;
    const uint32_t aDst = smb + (amRow * AST + ak4 * 8) * 2;
    const long   aItS = (long)64 * lda;       // src step for second chunk
    const uint32_t aItD = 64 * AST * 2;

    const __half* bSrc;
    uint32_t bDst, bItD;
    long bItS, bCst;
    if (BTRANS) {
        const int bk = tid >> 4, bn8 = tid & 15;
        bSrc = B + (long)bk * ldb + bn8 * 8;
        bDst = smb + 10240 + (bk * BSTT + bn8 * 8) * 2;
        bItS = (long)16 * ldb;  bItD = 16 * BSTT * 2;
        bCst = (long)32 * ldb;
    } else {
        bSrc = B + (long)amRow * ldb + ak4 * 8;
        bDst = smb + 10240 + (amRow * BSTN + ak4 * 8) * 2;
        bItS = (long)64 * ldb;  bItD = 64 * BSTN * 2;
        bCst = 32;
    }

    auto issue = [&](int c) {
        const uint32_t bo = (c & (S - 1)) * STG;
        const __half* as = aSrc + (long)c * 32;
        const __half* bs = bSrc + (long)c * bCst;
        cpa16(aDst + bo, as);            cpa16(aDst + bo + aItD, as + aItS);
        cpa16(bDst + bo, bs);            cpa16(bDst + bo + bItD, bs + bItS);
    };

    #pragma unroll
    for (int s = 0; s < S - 1; s++) {
        if (s < NC) issue(s);
        CP_COMMIT();
    }

    // fragment base addresses
    const int aR0 = mbase + (grp & 1) * 8 + li;
    const uint32_t aFrag = smb + (aR0 * AST + (grp >> 1) * 8) * 2;
    uint32_t bFrag;
    if (BTRANS) {
        const int kR0 = (grp & 1) * 8 + li;
        bFrag = smb + 10240 + (kR0 * BSTT + nbase + (grp >> 1) * 8) * 2;
    } else {
        const int nR0 = nbase + (grp >> 1) * 8 + li;
        bFrag = smb + 10240 + (nR0 * BSTN + (grp & 1) * 8) * 2;
    }

    float acc[4][4][4];
    #pragma unroll
    for (int i = 0; i < 4; i++)
        #pragma unroll
        for (int j = 0; j < 4; j++)
            #pragma unroll
            for (int q = 0; q < 4; q++) acc[i][j][q] = 0.f;

    for (int c = 0; c < NC; c++) {
        CP_WAIT(S - 2);
        __syncthreads();
        const uint32_t bo = (c & (S - 1)) * STG;
        #pragma unroll
        for (int ks = 0; ks < 2; ks++) {
            uint32_t a[4][4], bb[2][4];
            #pragma unroll
            for (int mt = 0; mt < 4; mt++)
                ldsm4(a[mt], aFrag + bo + mt * (16 * AST * 2) + ks * 32);
            #pragma unroll
            for (int np = 0; np < 2; np++) {
                if (BTRANS) ldsm4t(bb[np], bFrag + bo + ks * (16 * BSTT * 2) + np * 32);
                else        ldsm4 (bb[np], bFrag + bo + np * (16 * BSTN * 2) + ks * 32);
            }
            #pragma unroll
            for (int mt = 0; mt < 4; mt++)
                #pragma unroll
                for (int nt = 0; nt < 4; nt++)
                    mma16(acc[mt][nt], a[mt], &bb[nt >> 1][(nt & 1) * 2]);
        }
        const int nx = c + S - 1;
        if (nx < NC) issue(nx);
        CP_COMMIT();
    }

    // epilogue
    #pragma unroll
    for (int mt = 0; mt < 4; mt++) {
        const int r0 = mbase + mt * 16 + g;
        #pragma unroll
        for (int nt = 0; nt < 4; nt++) {
            const int cc = nbase + nt * 8 + 2 * t;
            float bx = 0.f, byv = 0.f;
            if (BIAS) { bx = bias[col0 + cc]; byv = bias[col0 + cc + 1]; }
            float v00 = acc[mt][nt][0] * scale + bx;
            float v01 = acc[mt][nt][1] * scale + byv;
            float v10 = acc[mt][nt][2] * scale + bx;
            float v11 = acc[mt][nt][3] * scale + byv;
            if constexpr (sizeof(TC) == 2) {
                *(__half2*)((__half*)C + (long)r0 * ldc + cc) = __floats2half2_rn(v00, v01);
                *(__half2*)((__half*)C + (long)(r0 + 8) * ldc + cc) = __floats2half2_rn(v10, v11);
            } else {
                *(float2*)((float*)C + (long)r0 * ldc + cc) = make_float2(v00, v01);
                *(float2*)((float*)C + (long)(r0 + 8) * ldc + cc) = make_float2(v10, v11);
            }
        }
    }
}

// ---------------------------------------------------------------------------
// Causal softmax: fp32 scores -> normalized fp16 P. Writes only up to the
// 128-aligned block end (all the P@V kernel ever reads). Shuffle reductions.
// ---------------------------------------------------------------------------
__global__ __launch_bounds__(256) void softmax_causal_k(
    const float* __restrict__ scores, __half* __restrict__ P)
{
    const int tq = blockIdx.x, b = blockIdx.y;
    const float* row = scores + ((size_t)b * T_SEQ + tq) * T_SEQ;
    __half* prow = P + ((size_t)b * T_SEQ + tq) * T_SEQ;
    const int n = tq + 1;
    const int nw = ((tq >> 7) + 1) << 7;
    const int tid = threadIdx.x, wid = tid >> 5, lane = tid & 31;

    __shared__ float red[8];

    float e[8];
    float m = -INFINITY;
    #pragma unroll
    for (int j = 0; j < 8; j++) {
        const int i = tid + j * 256;
        e[j] = (i < n) ? row[i] : -INFINITY;
        m = fmaxf(m, e[j]);
    }
    #pragma unroll
    for (int o = 16; o; o >>= 1) m = fmaxf(m, __shfl_xor_sync(~0u, m, o));
    if (lane == 0) red[wid] = m;
    __syncthreads();
    m = red[0];
    #pragma unroll
    for (int w = 1; w < 8; w++) m = fmaxf(m, red[w]);

    float s = 0.f;
    #pragma unroll
    for (int j = 0; j < 8; j++) { e[j] = __expf(e[j] - m); s += e[j]; }
    #pragma unroll
    for (int o = 16; o; o >>= 1) s += __shfl_xor_sync(~0u, s, o);
    __syncthreads();                       // red reads done before overwrite
    if (lane == 0) red[wid] = s;
    __syncthreads();
    s = 0.f;
    #pragma unroll
    for (int w = 0; w < 8; w++) s += red[w];
    const float inv = 1.f / s;

    #pragma unroll
    for (int j = 0; j < 8; j++) {
        const int i = tid + j * 256;
        if (i < nw) prow[i] = __float2half_rn(e[j] * inv);
    }
}

// fp32 -> fp16 bulk convert, 8 elems/thread
__global__ __launch_bounds__(256) void cvt_k(
    const float* __restrict__ in, __half* __restrict__ out)
{
    const size_t i = ((size_t)blockIdx.x * 256 + threadIdx.x) * 8;
    float4 v0 = *(const float4*)(in + i);
    float4 v1 = *(const float4*)(in + i + 4);
    uint4 o;
    o.x = pack2(v0.x, v0.y); o.y = pack2(v0.z, v0.w);
    o.z = pack2(v1.x, v1.y); o.w = pack2(v1.z, v1.w);
    *(uint4*)(out + i) = o;
}

extern "C" void kernel_launch(void* const* d_in, const int* in_sizes, int n_in,
                              void* d_out, int out_size)
{
    (void)in_sizes; (void)n_in; (void)out_size;
    const float* x      = (const float*)d_in[0];  // [4,2048,1024]
    const float* w_qkv  = (const float*)d_in[1];  // [1024,3072]
    const float* w_proj = (const float*)d_in[2];  // [1024,1024]
    const float* b_proj = (const float*)d_in[3];  // [1024]
    float* out          = (float*)d_out;          // [4,2048,1024]

    __half *xh, *wqkvh, *wprojh, *qkv, *p, *att;
    float *scores;
    cudaGetSymbolAddress((void**)&xh,     g_xh);
    cudaGetSymbolAddress((void**)&wqkvh,  g_wqkvh);
    cudaGetSymbolAddress((void**)&wprojh, g_wprojh);
    cudaGetSymbolAddress((void**)&qkv,    g_qkv);
    cudaGetSymbolAddress((void**)&scores, g_scores);
    cudaGetSymbolAddress((void**)&p,      g_p);
    cudaGetSymbolAddress((void**)&att,    g_att);

    const int D = D_MODEL, T = T_SEQ;
    const int SMEM = 4 * 20480;  // 81920
    const dim3 blk(256);

    cudaFuncSetAttribute((const void*)mm_h<__half, 1, false, false, false, false>,
                         cudaFuncAttributeMaxDynamicSharedMemorySize, SMEM);
    cudaFuncSetAttribute((const void*)mm_h<float, 0, true, false, false, true>,
                         cudaFuncAttributeMaxDynamicSharedMemorySize, SMEM);
    cudaFuncSetAttribute((const void*)mm_h<__half, 1, false, true, false, true>,
                         cudaFuncAttributeMaxDynamicSharedMemorySize, SMEM);
    cudaFuncSetAttribute((const void*)mm_h<float, 1, false, false, true, false>,
                         cudaFuncAttributeMaxDynamicSharedMemorySize, SMEM);

    // 0) fp32 -> fp16 conversions
    cvt_k<<<(B_BATCH * T * D) / 2048, blk>>>(x, xh);
    cvt_k<<<(D * 3 * D) / 2048, blk>>>(w_qkv, wqkvh);
    cvt_k<<<(D * D) / 2048, blk>>>(w_proj, wprojh);

    // 1) QKV = Xh @ Wqkv -> fp16 : [8192,3072], K=1024, B [K,N]
    mm_h<__half, 1, false, false, false, false>
        <<<dim3(3 * D / 128, B_BATCH * T / 128, 1), blk, SMEM>>>(
        xh, wqkvh, qkv, nullptr, D, D, 3 * D, 3 * D, 0, 0, 0, 1.f);

    // 2) scores = Q @ K^T / 32 (fp32), causal cull, heavy-first; K-matrix [N,K]
    mm_h<float, 0, true, false, false, true>
        <<<dim3(T / 128, T / 128, B_BATCH), blk, SMEM>>>(
        qkv, qkv + D, scores, nullptr, D, 3 * D, 3 * D, T,
        (long)T * 3 * D, (long)T * 3 * D, (long)T * T, 1.f / 32.f);

    // 3) causal softmax -> fp16 P (tail zero up to 128-block end)
    softmax_causal_k<<<dim3(T, B_BATCH), blk>>>(scores, p);

    // 4) att = P @ V -> fp16 : causal K-end, heavy-first; V [K,N]
    mm_h<__half, 1, false, true, false, true>
        <<<dim3(D / 128, T / 128, B_BATCH), blk, SMEM>>>(
        p, qkv + 2 * D, att, nullptr, T, T, 3 * D, D,
        (long)T * T, (long)T * 3 * D, (long)T * D, 1.f);

    // 5) out = att @ Wproj + b : [8192,1024], K=1024, B [K,N]
    mm_h<float, 1, false, false, true, false>
        <<<dim3(D / 128, B_BATCH * T / 128, 1), blk, SMEM>>>(
        att, wprojh, out, b_proj, D, D, D, D, 0, 0, 0, 1.f);
}